// round 4
// baseline (speedup 1.0000x reference)
#include <cuda_runtime.h>
#include <math.h>

#define BB   16
#define NN   2048
#define DD   142
#define KNB  10
#define MD   16
#define EH   610
#define CPAD 640
#define GN   8
#define RR   (GN*KNB)
#define ETH  160

typedef unsigned long long u64;

__device__ int   g_idx [BB*NN*KNB];
__device__ float g_dist[BB*NN*KNB];
__device__ float g_mi  [BB*NN*MD];
__device__ float g_part[(BB*NN/8)*DD];
__device__ float g_base[(size_t)BB*NN*CPAD];
__device__ float g_P   [(size_t)BB*NN*CPAD];

__device__ __forceinline__ float silu(float x) { return x / (1.f + __expf(-x)); }

__device__ __forceinline__ u64 pack2(float x, float y) {
    u64 r;
    asm("mov.b64 %0, {%1, %2};" : "=l"(r) : "f"(x), "f"(y));
    return r;
}
__device__ __forceinline__ void fma2(u64 &d, u64 a, u64 b) {
    asm("fma.rn.f32x2 %0, %1, %2, %0;" : "+l"(d) : "l"(a), "l"(b));
}
__device__ __forceinline__ void add2(u64 &d, u64 a) {
    asm("add.rn.f32x2 %0, %0, %1;" : "+l"(d) : "l"(a));
}
__device__ __forceinline__ float2 unpack2(u64 v) {
    float2 r;
    asm("mov.b64 {%0, %1}, %2;" : "=f"(r.x), "=f"(r.y) : "l"(v));
    return r;
}

// ---------------- kernel 1: KNN, warp-local top-10 + single merge ----------
__global__ void __launch_bounds__(256) knn_kernel(const float* __restrict__ coors) {
    __shared__ float candv[8][KNB];
    __shared__ int   candi[8][KNB];
    int bi = blockIdx.x;
    int b  = bi >> 11;
    int i  = bi & (NN - 1);
    int tid = threadIdx.x, lane = tid & 31, warp = tid >> 5;
    const float* cb = coors + (size_t)b * NN * 3;
    float cx = cb[i*3+0], cy = cb[i*3+1], cz = cb[i*3+2];
    float vals[8];
    #pragma unroll
    for (int u = 0; u < 8; u++) {
        int j = warp * 256 + u * 32 + lane;
        float dx = cx - cb[j*3+0];
        float dy = cy - cb[j*3+1];
        float dz = cz - cb[j*3+2];
        vals[u] = dx*dx + dy*dy + dz*dz;
    }
    // warp-local successive minima (sorted ascending), no block syncs
    for (int t = 0; t < KNB; t++) {
        float bv = INFINITY; int bj = 0x7fffffff;
        #pragma unroll
        for (int u = 0; u < 8; u++) {
            float v = vals[u]; int j = warp * 256 + u * 32 + lane;
            if (v < bv || (v == bv && j < bj)) { bv = v; bj = j; }
        }
        #pragma unroll
        for (int off = 16; off; off >>= 1) {
            float ov = __shfl_xor_sync(0xffffffffu, bv, off);
            int   oj = __shfl_xor_sync(0xffffffffu, bj, off);
            if (ov < bv || (ov == bv && oj < bj)) { bv = ov; bj = oj; }
        }
        // invalidate winner at its owner lane
        #pragma unroll
        for (int u = 0; u < 8; u++)
            if (lane == (bj & 31) && u == ((bj >> 5) & 7)) vals[u] = INFINITY;
        if (lane == 0) { candv[warp][t] = bv; candi[warp][t] = bj; }
    }
    __syncthreads();
    if (tid == 0) {
        int h0=0,h1=0,h2=0,h3=0,h4=0,h5=0,h6=0,h7=0;
        #pragma unroll
        for (int t = 0; t < KNB; t++) {
            float bv = INFINITY; int bj = 0x7fffffff; int bw = -1;
            #define TRY(w, hw) { if (hw < KNB) { float v = candv[w][hw]; int jx = candi[w][hw]; \
                if (v < bv || (v == bv && jx < bj)) { bv = v; bj = jx; bw = w; } } }
            TRY(0,h0) TRY(1,h1) TRY(2,h2) TRY(3,h3)
            TRY(4,h4) TRY(5,h5) TRY(6,h6) TRY(7,h7)
            #undef TRY
            g_idx [bi*KNB + t] = bj;
            g_dist[bi*KNB + t] = bv;
            if      (bw == 0) h0++;
            else if (bw == 1) h1++;
            else if (bw == 2) h2++;
            else if (bw == 3) h3++;
            else if (bw == 4) h4++;
            else if (bw == 5) h5++;
            else if (bw == 6) h6++;
            else              h7++;
        }
    }
}

// ---------------- kernel 2: prep GEMM (base & P), 128x64 tiles --------------
__global__ void __launch_bounds__(256)
prep_kernel(const float* __restrict__ feats,
            const float* __restrict__ We1, const float* __restrict__ be1) {
    __shared__ __align__(16) float As2[128][18];
    __shared__ __align__(16) float Bs[16][64];
    int tid = threadIdx.x;
    int tx = tid & 7, ty = tid >> 3;
    int ct = blockIdx.x;
    int half = (ct >= 10);
    int colbase = (half ? ct - 10 : ct) * 64;
    size_t n0 = (size_t)blockIdx.y * 128;
    int wrow0 = half ? 142 : 0;

    u64 acc[4][4];
    #pragma unroll
    for (int i = 0; i < 4; i++)
        #pragma unroll
        for (int j = 0; j < 4; j++) acc[i][j] = 0ull;

    for (int k0 = 0; k0 < DD; k0 += 16) {
        #pragma unroll
        for (int p = 0; p < 4; p++) {
            int idx = tid + p * 256;
            int node = idx >> 3, kp = (idx & 7) * 2;
            int k = k0 + kp;
            float2 v = make_float2(0.f, 0.f);
            if (k < DD)
                v = *(const float2*)(feats + (n0 + node) * DD + k);
            As2[node][kp] = v.x; As2[node][kp+1] = v.y;
        }
        #pragma unroll
        for (int p = 0; p < 2; p++) {
            int idx = tid + p * 256;
            int kk = idx >> 5, cpos = (idx & 31) * 2;
            int k = k0 + kk;
            float2 v = make_float2(0.f, 0.f);
            if (k < DD && colbase + cpos + 1 < EH)
                v = *(const float2*)(We1 + (size_t)(wrow0 + k) * EH + colbase + cpos);
            else if (k < DD && colbase + cpos < EH)
                v.x = We1[(size_t)(wrow0 + k) * EH + colbase + cpos];
            Bs[kk][cpos] = v.x; Bs[kk][cpos+1] = v.y;
        }
        __syncthreads();
        #pragma unroll
        for (int kk = 0; kk < 16; kk++) {
            ulonglong2 w01 = *(const ulonglong2*)&Bs[kk][tx*8];
            ulonglong2 w23 = *(const ulonglong2*)&Bs[kk][tx*8+4];
            #pragma unroll
            for (int i = 0; i < 4; i++) {
                float a = As2[ty*4 + i][kk];
                u64 pa = pack2(a, a);
                fma2(acc[i][0], pa, w01.x);
                fma2(acc[i][1], pa, w01.y);
                fma2(acc[i][2], pa, w23.x);
                fma2(acc[i][3], pa, w23.y);
            }
        }
        __syncthreads();
    }

    float* outp = half ? g_P : g_base;
    #pragma unroll
    for (int i = 0; i < 4; i++) {
        size_t node = n0 + ty*4 + i;
        float ov[8];
        #pragma unroll
        for (int j = 0; j < 4; j++) {
            float2 v = unpack2(acc[i][j]);
            ov[2*j] = v.x; ov[2*j+1] = v.y;
        }
        #pragma unroll
        for (int j = 0; j < 8; j++) {
            int cl = colbase + tx*8 + j;
            float val = 0.f;
            if (cl < EH) {
                val = ov[j];
                if (!half) val += be1[cl];
            }
            ov[j] = val;
        }
        float* op = outp + node * CPAD + colbase + tx*8;
        *(float4*)op       = make_float4(ov[0], ov[1], ov[2], ov[3]);
        *(float4*)(op + 4) = make_float4(ov[4], ov[5], ov[6], ov[7]);
    }
}

// ---------------- kernel 3: per-edge residual + GEMM2 + m_i ------------------
__global__ void __launch_bounds__(ETH)
edge_kernel(const float* __restrict__ We1, const float* __restrict__ We2,
            const float* __restrict__ be2) {
    __shared__ int   sj [RR];
    __shared__ float sdt[RR];
    __shared__ __align__(16) float df_s[RR*24];
    __shared__ __align__(16) float wd_s[21*64];
    __shared__ __align__(16) float we2_s[64*MD];
    __shared__ __align__(16) float base_s[GN*64];
    __shared__ float Ms[RR*MD];

    int tid = threadIdx.x;
    int base_gn = blockIdx.x * GN;
    int b = base_gn >> 11;
    int cg = tid & 3;
    int pp = tid >> 2;
    int g  = pp / 5;
    int pl = pp % 5;
    int e0 = g * 10 + 2 * pl;
    int e1 = e0 + 1;

    if (tid < RR) {
        sj [tid] = g_idx [base_gn*KNB + tid];
        sdt[tid] = g_dist[base_gn*KNB + tid];
    }
    __syncthreads();

    for (int v = tid; v < RR*21; v += ETH) {
        int ee = v / 21, t = v - ee*21;
        float d = sdt[ee];
        float f;
        if (t < 10)      f = sinf(ldexpf(d, -t));
        else if (t < 20) f = cosf(ldexpf(d, -(t-10)));
        else             f = d;
        df_s[ee*24 + t] = f;
    }

    size_t jg0 = (size_t)((b << 11) + sj[e0]);
    size_t jg1 = (size_t)((b << 11) + sj[e1]);
    u64 macc0[8] = {0,0,0,0,0,0,0,0};
    u64 macc1[8] = {0,0,0,0,0,0,0,0};

    for (int chunk = 0; chunk < 10; chunk++) {
        int c0 = chunk * 64;
        for (int v = tid; v < 21*32; v += ETH) {
            int t = v / 32, c = (v - t*32) * 2;
            int col = c0 + c;
            float2 w = make_float2(0.f, 0.f);
            if (col + 1 < EH)
                w = *(const float2*)(We1 + (size_t)(284 + t) * EH + col);
            else if (col < EH)
                w.x = We1[(size_t)(284 + t) * EH + col];
            wd_s[t*64 + c] = w.x; wd_s[t*64 + c + 1] = w.y;
        }
        for (int v = tid; v < 64*MD/4; v += ETH) {
            int off = v * 4;
            int col = c0 + (off >> 4);
            float4 w = make_float4(0.f,0.f,0.f,0.f);
            if (col < EH)
                w = *(const float4*)(We2 + (size_t)c0 * MD + off);
            *(float4*)(we2_s + off) = w;
        }
        for (int v = tid; v < GN*64/4; v += ETH) {
            int off = v * 4;
            int gg = off >> 6;
            *(float4*)(base_s + off) =
                *(const float4*)(g_base + (size_t)(base_gn + gg) * CPAD + c0 + (off & 63));
        }
        __syncthreads();

        const float* bp = base_s + g*64 + cg*16;
        const float4* pr0 = (const float4*)(g_P + jg0 * CPAD + c0 + cg*16);
        const float4* pr1 = (const float4*)(g_P + jg1 * CPAD + c0 + cg*16);
        u64 h0[8], h1[8];
        #pragma unroll
        for (int q = 0; q < 4; q++) {
            float4 p0 = pr0[q], p1 = pr1[q];
            float b0 = bp[4*q], b1 = bp[4*q+1], b2 = bp[4*q+2], b3 = bp[4*q+3];
            h0[2*q]   = pack2(b0 + p0.x, b1 + p0.y);
            h0[2*q+1] = pack2(b2 + p0.z, b3 + p0.w);
            h1[2*q]   = pack2(b0 + p1.x, b1 + p1.y);
            h1[2*q+1] = pack2(b2 + p1.z, b3 + p1.w);
        }

        const float* dfp0 = df_s + e0*24;
        const float* dfp1 = df_s + e1*24;
        #pragma unroll
        for (int t = 0; t < 21; t++) {
            const ulonglong2* wr = (const ulonglong2*)(wd_s + t*64 + cg*16);
            u64 d0 = pack2(dfp0[t], dfp0[t]);
            u64 d1 = pack2(dfp1[t], dfp1[t]);
            ulonglong2 wA = wr[0], wB = wr[1], wC = wr[2], wD = wr[3];
            fma2(h0[0], d0, wA.x); fma2(h0[1], d0, wA.y);
            fma2(h0[2], d0, wB.x); fma2(h0[3], d0, wB.y);
            fma2(h0[4], d0, wC.x); fma2(h0[5], d0, wC.y);
            fma2(h0[6], d0, wD.x); fma2(h0[7], d0, wD.y);
            fma2(h1[0], d1, wA.x); fma2(h1[1], d1, wA.y);
            fma2(h1[2], d1, wB.x); fma2(h1[3], d1, wB.y);
            fma2(h1[4], d1, wC.x); fma2(h1[5], d1, wC.y);
            fma2(h1[6], d1, wD.x); fma2(h1[7], d1, wD.y);
        }
        #pragma unroll
        for (int cp = 0; cp < 8; cp++) {
            const ulonglong2* wp = (const ulonglong2*)(we2_s + (cg*16 + 2*cp) * MD);
            float2 v0 = unpack2(h0[cp]);
            float2 v1 = unpack2(h1[cp]);
            float s00 = silu(v0.x), s01 = silu(v0.y);
            float s10 = silu(v1.x), s11 = silu(v1.y);
            u64 x00 = pack2(s00, s00), x01 = pack2(s01, s01);
            u64 x10 = pack2(s10, s10), x11 = pack2(s11, s11);
            {   // row r (cols 0..15), multiplies x?0
                ulonglong2 a0 = wp[0], a1 = wp[1], a2 = wp[2], a3 = wp[3];
                fma2(macc0[0], x00, a0.x); fma2(macc0[1], x00, a0.y);
                fma2(macc0[2], x00, a1.x); fma2(macc0[3], x00, a1.y);
                fma2(macc0[4], x00, a2.x); fma2(macc0[5], x00, a2.y);
                fma2(macc0[6], x00, a3.x); fma2(macc0[7], x00, a3.y);
                fma2(macc1[0], x10, a0.x); fma2(macc1[1], x10, a0.y);
                fma2(macc1[2], x10, a1.x); fma2(macc1[3], x10, a1.y);
                fma2(macc1[4], x10, a2.x); fma2(macc1[5], x10, a2.y);
                fma2(macc1[6], x10, a3.x); fma2(macc1[7], x10, a3.y);
            }
            {   // row r+1, multiplies x?1
                ulonglong2 b0 = wp[4], b1 = wp[5], b2 = wp[6], b3 = wp[7];
                fma2(macc0[0], x01, b0.x); fma2(macc0[1], x01, b0.y);
                fma2(macc0[2], x01, b1.x); fma2(macc0[3], x01, b1.y);
                fma2(macc0[4], x01, b2.x); fma2(macc0[5], x01, b2.y);
                fma2(macc0[6], x01, b3.x); fma2(macc0[7], x01, b3.y);
                fma2(macc1[0], x11, b0.x); fma2(macc1[1], x11, b0.y);
                fma2(macc1[2], x11, b1.x); fma2(macc1[3], x11, b1.y);
                fma2(macc1[4], x11, b2.x); fma2(macc1[5], x11, b2.y);
                fma2(macc1[6], x11, b3.x); fma2(macc1[7], x11, b3.y);
            }
        }
        __syncthreads();
    }

    #pragma unroll
    for (int mp = 0; mp < 8; mp++) {
        add2(macc0[mp], __shfl_xor_sync(0xffffffffu, macc0[mp], 1));
        add2(macc0[mp], __shfl_xor_sync(0xffffffffu, macc0[mp], 2));
        add2(macc1[mp], __shfl_xor_sync(0xffffffffu, macc1[mp], 1));
        add2(macc1[mp], __shfl_xor_sync(0xffffffffu, macc1[mp], 2));
    }
    if (cg == 0) {
        #pragma unroll
        for (int mp = 0; mp < 8; mp++) {
            float2 v0 = unpack2(macc0[mp]);
            float2 v1 = unpack2(macc1[mp]);
            float bb0 = be2[2*mp], bb1 = be2[2*mp+1];
            Ms[e0*MD + 2*mp]     = silu(v0.x + bb0);
            Ms[e0*MD + 2*mp + 1] = silu(v0.y + bb1);
            Ms[e1*MD + 2*mp]     = silu(v1.x + bb0);
            Ms[e1*MD + 2*mp + 1] = silu(v1.y + bb1);
        }
    }
    __syncthreads();
    if (tid < GN*MD) {
        int gg = tid >> 4, m = tid & 15;
        float s = 0.f;
        #pragma unroll
        for (int k2 = 0; k2 < KNB; k2++) s += Ms[(gg*KNB + k2)*MD + m];
        g_mi[(size_t)(base_gn + gg)*MD + m] = s;
    }
}

// ---------------- kernel 4: LayerNorm + node MLP (vectorized K loops) -------
__global__ void __launch_bounds__(256)
node_kernel(const float* __restrict__ feats,
            const float* __restrict__ lng, const float* __restrict__ lnb,
            const float* __restrict__ Wn1, const float* __restrict__ bn1,
            const float* __restrict__ Wn2, const float* __restrict__ bn2) {
    __shared__ __align__(16) float in_s[8 * 160];
    __shared__ __align__(16) float h_s [8 * 288];
    int tid = threadIdx.x;
    int base_gn = blockIdx.x * 8;
    int w = tid >> 5, lane = tid & 31;

    {
        int gn = base_gn + w;
        const float* fp = feats + (size_t)gn * DD;
        float s = 0.f, ss = 0.f;
        float vals[5];
        #pragma unroll
        for (int u = 0; u < 5; u++) {
            int c = lane + u * 32;
            float v = (c < DD) ? fp[c] : 0.f;
            vals[u] = v; s += v; ss += v * v;
        }
        #pragma unroll
        for (int o = 16; o; o >>= 1) {
            s  += __shfl_xor_sync(0xffffffffu, s,  o);
            ss += __shfl_xor_sync(0xffffffffu, ss, o);
        }
        float mu  = s * (1.f / DD);
        float var = ss * (1.f / DD) - mu * mu;
        float inv = rsqrtf(var + 1e-5f);
        #pragma unroll
        for (int u = 0; u < 5; u++) {
            int c = lane + u * 32;
            if (c < DD) in_s[w * 160 + c] = (vals[u] - mu) * inv * lng[c] + lnb[c];
        }
        if (lane < MD) in_s[w * 160 + DD + lane] = g_mi[(size_t)gn * MD + lane];
    }
    __syncthreads();

    // stage 1: 2 nodes x 4 cols; K chunked by 4 with float4 input loads
    for (int o = tid; o < 284; o += 256) {
        int ng  = o & 3;
        int cgi = o >> 2;
        int c = cgi * 4;
        const float* ip0 = in_s + (2*ng) * 160;
        const float* ip1 = ip0 + 160;
        u64 a00 = pack2(bn1[c],   bn1[c+1]);
        u64 a01 = pack2(bn1[c+2], bn1[c+3]);
        u64 a10 = a00, a11 = a01;
        #pragma unroll 2
        for (int k0 = 0; k0 < 156; k0 += 4) {
            float4 x0 = *(const float4*)(ip0 + k0);
            float4 x1 = *(const float4*)(ip1 + k0);
            const float* wrow = Wn1 + (size_t)k0 * 284 + c;
            ulonglong2 w0 = *(const ulonglong2*)(wrow);
            ulonglong2 w1 = *(const ulonglong2*)(wrow + 284);
            ulonglong2 w2 = *(const ulonglong2*)(wrow + 568);
            ulonglong2 w3 = *(const ulonglong2*)(wrow + 852);
            u64 p;
            p = pack2(x0.x, x0.x); fma2(a00, p, w0.x); fma2(a01, p, w0.y);
            p = pack2(x1.x, x1.x); fma2(a10, p, w0.x); fma2(a11, p, w0.y);
            p = pack2(x0.y, x0.y); fma2(a00, p, w1.x); fma2(a01, p, w1.y);
            p = pack2(x1.y, x1.y); fma2(a10, p, w1.x); fma2(a11, p, w1.y);
            p = pack2(x0.z, x0.z); fma2(a00, p, w2.x); fma2(a01, p, w2.y);
            p = pack2(x1.z, x1.z); fma2(a10, p, w2.x); fma2(a11, p, w2.y);
            p = pack2(x0.w, x0.w); fma2(a00, p, w3.x); fma2(a01, p, w3.y);
            p = pack2(x1.w, x1.w); fma2(a10, p, w3.x); fma2(a11, p, w3.y);
        }
        #pragma unroll
        for (int kk = 156; kk < 158; kk++) {
            ulonglong2 ww = *(const ulonglong2*)(Wn1 + (size_t)kk * 284 + c);
            u64 x0 = pack2(ip0[kk], ip0[kk]);
            u64 x1 = pack2(ip1[kk], ip1[kk]);
            fma2(a00, x0, ww.x); fma2(a01, x0, ww.y);
            fma2(a10, x1, ww.x); fma2(a11, x1, ww.y);
        }
        float2 v;
        float* hp0 = h_s + (2*ng) * 288 + c;
        float* hp1 = hp0 + 288;
        v = unpack2(a00); hp0[0] = silu(v.x); hp0[1] = silu(v.y);
        v = unpack2(a01); hp0[2] = silu(v.x); hp0[3] = silu(v.y);
        v = unpack2(a10); hp1[0] = silu(v.x); hp1[1] = silu(v.y);
        v = unpack2(a11); hp1[2] = silu(v.x); hp1[3] = silu(v.y);
    }
    __syncthreads();

    // stage 2: 2 nodes x 2 cols; K chunked by 4 with float4 input loads
    for (int o = tid; o < 284; o += 256) {
        int ng  = o & 3;
        int cgi = o >> 2;
        int c = cgi * 2;
        const float* hp0 = h_s + (2*ng) * 288;
        const float* hp1 = hp0 + 288;
        u64 a0 = pack2(bn2[c], bn2[c+1]);
        u64 a1 = a0;
        #pragma unroll 2
        for (int k0 = 0; k0 < 284; k0 += 4) {
            float4 x0 = *(const float4*)(hp0 + k0);
            float4 x1 = *(const float4*)(hp1 + k0);
            const float* wrow = Wn2 + (size_t)k0 * DD + c;
            u64 w0 = *(const u64*)(wrow);
            u64 w1 = *(const u64*)(wrow + DD);
            u64 w2 = *(const u64*)(wrow + 2*DD);
            u64 w3 = *(const u64*)(wrow + 3*DD);
            u64 p;
            p = pack2(x0.x, x0.x); fma2(a0, p, w0);
            p = pack2(x1.x, x1.x); fma2(a1, p, w0);
            p = pack2(x0.y, x0.y); fma2(a0, p, w1);
            p = pack2(x1.y, x1.y); fma2(a1, p, w1);
            p = pack2(x0.z, x0.z); fma2(a0, p, w2);
            p = pack2(x1.z, x1.z); fma2(a1, p, w2);
            p = pack2(x0.w, x0.w); fma2(a0, p, w3);
            p = pack2(x1.w, x1.w); fma2(a1, p, w3);
        }
        size_t gn0 = base_gn + 2*ng;
        float2 v0 = unpack2(a0);
        float2 v1 = unpack2(a1);
        in_s[(2*ng)*160 + c]       = v0.x + feats[gn0 * DD + c];
        in_s[(2*ng)*160 + c + 1]   = v0.y + feats[gn0 * DD + c + 1];
        in_s[(2*ng+1)*160 + c]     = v1.x + feats[(gn0+1) * DD + c];
        in_s[(2*ng+1)*160 + c + 1] = v1.y + feats[(gn0+1) * DD + c + 1];
    }
    __syncthreads();

    for (int c = tid; c < DD; c += 256) {
        float s = 0.f;
        #pragma unroll
        for (int gg = 0; gg < 8; gg++) s += in_s[gg * 160 + c];
        g_part[(size_t)blockIdx.x * DD + c] = s;
    }
}

// ---------------- kernel 5: pool + head --------------------------------------
__global__ void head_kernel(const float* __restrict__ Wout,
                            const float* __restrict__ bout,
                            float* __restrict__ out) {
    __shared__ float red[256];
    int b = blockIdx.x, tid = threadIdx.x;
    const int blocksPerBatch = NN / 8;
    float v = 0.f;
    if (tid < DD) {
        float s = 0.f;
        const float* pp = g_part + ((size_t)b * blocksPerBatch) * DD + tid;
        for (int blk = 0; blk < blocksPerBatch; blk++) s += pp[(size_t)blk * DD];
        float emb = s * (1.f / (float)NN);
        v = emb * Wout[tid];
    }
    red[tid] = v;
    __syncthreads();
    for (int s2 = 128; s2 > 0; s2 >>= 1) {
        if (tid < s2) red[tid] += red[tid + s2];
        __syncthreads();
    }
    if (tid == 0) out[b] = red[0] + bout[0];
}

// ---------------- launch ----------------------------------------------------
extern "C" void kernel_launch(void* const* d_in, const int* in_sizes, int n_in,
                              void* d_out, int out_size) {
    const float* feats = (const float*)d_in[0];
    const float* coors = (const float*)d_in[1];
    const float* We1  = (const float*)d_in[3];
    const float* be1  = (const float*)d_in[4];
    const float* We2  = (const float*)d_in[5];
    const float* be2  = (const float*)d_in[6];
    const float* lng  = (const float*)d_in[11];
    const float* lnb  = (const float*)d_in[12];
    const float* Wn1  = (const float*)d_in[13];
    const float* bn1  = (const float*)d_in[14];
    const float* Wn2  = (const float*)d_in[15];
    const float* bn2  = (const float*)d_in[16];
    const float* Wout = (const float*)d_in[17];
    const float* bout = (const float*)d_in[18];
    float* out = (float*)d_out;

    knn_kernel<<<BB * NN, 256>>>(coors);
    dim3 pg(20, 256);
    prep_kernel<<<pg, 256>>>(feats, We1, be1);
    edge_kernel<<<(BB * NN) / GN, ETH>>>(We1, We2, be2);
    node_kernel<<<(BB * NN) / 8, 256>>>(feats, lng, lnb, Wn1, bn1, Wn2, bn2);
    head_kernel<<<BB, 256>>>(Wout, bout, out);
}

// round 5
// speedup vs baseline: 1.2087x; 1.2087x over previous
#include <cuda_runtime.h>
#include <math.h>

#define BB   16
#define NN   2048
#define DD   142
#define KNB  10
#define MD   16
#define EH   610
#define CPAD 640
#define GN   8
#define RR   (GN*KNB)
#define ETH  160

typedef unsigned long long u64;

__device__ int   g_idx [BB*NN*KNB];
__device__ float g_dist[BB*NN*KNB];
__device__ float g_mi  [BB*NN*MD];
__device__ float g_hpart[(BB*NN/8)*284];
__device__ float g_fpart[(BB*NN/8)*DD];
__device__ float g_base[(size_t)BB*NN*CPAD];
__device__ float g_P   [(size_t)BB*NN*CPAD];

__device__ __forceinline__ float silu(float x) { return x / (1.f + __expf(-x)); }

__device__ __forceinline__ u64 pack2(float x, float y) {
    u64 r;
    asm("mov.b64 %0, {%1, %2};" : "=l"(r) : "f"(x), "f"(y));
    return r;
}
__device__ __forceinline__ void fma2(u64 &d, u64 a, u64 b) {
    asm("fma.rn.f32x2 %0, %1, %2, %0;" : "+l"(d) : "l"(a), "l"(b));
}
__device__ __forceinline__ void add2(u64 &d, u64 a) {
    asm("add.rn.f32x2 %0, %0, %1;" : "+l"(d) : "l"(a));
}
__device__ __forceinline__ float2 unpack2(u64 v) {
    float2 r;
    asm("mov.b64 {%0, %1}, %2;" : "=f"(r.x), "=f"(r.y) : "l"(v));
    return r;
}

// ---------------- kernel 1: KNN (regs + warp shuffle) -----------------------
__global__ void __launch_bounds__(256) knn_kernel(const float* __restrict__ coors) {
    __shared__ float swv[8];
    __shared__ int   swi[8];
    __shared__ int   s_win;
    int bi = blockIdx.x;
    int b  = bi >> 11;
    int i  = bi & (NN - 1);
    int tid = threadIdx.x, lane = tid & 31, warp = tid >> 5;
    const float* cb = coors + (size_t)b * NN * 3;
    float cx = cb[i*3+0], cy = cb[i*3+1], cz = cb[i*3+2];
    float vals[8];
    #pragma unroll
    for (int u = 0; u < 8; u++) {
        int j = u * 256 + tid;
        float dx = cx - cb[j*3+0];
        float dy = cy - cb[j*3+1];
        float dz = cz - cb[j*3+2];
        vals[u] = dx*dx + dy*dy + dz*dz;
    }
    for (int t = 0; t < KNB; t++) {
        float bv = vals[0]; int bj = tid;
        #pragma unroll
        for (int u = 1; u < 8; u++) {
            float v = vals[u]; int j = u * 256 + tid;
            if (v < bv) { bv = v; bj = j; }
        }
        #pragma unroll
        for (int off = 16; off; off >>= 1) {
            float ov = __shfl_down_sync(0xffffffffu, bv, off);
            int   oj = __shfl_down_sync(0xffffffffu, bj, off);
            if (ov < bv || (ov == bv && oj < bj)) { bv = ov; bj = oj; }
        }
        if (lane == 0) { swv[warp] = bv; swi[warp] = bj; }
        __syncthreads();
        if (tid == 0) {
            float fv = swv[0]; int fj = swi[0];
            #pragma unroll
            for (int w = 1; w < 8; w++) {
                float ov = swv[w]; int oj = swi[w];
                if (ov < fv || (ov == fv && oj < fj)) { fv = ov; fj = oj; }
            }
            g_idx [bi*KNB + t] = fj;
            g_dist[bi*KNB + t] = fv;
            s_win = fj;
        }
        __syncthreads();
        int wj = s_win;
        if ((wj & 255) == tid) vals[wj >> 8] = INFINITY;
    }
}

// ---------------- kernel 2: prep GEMM (base & P), 128x64 tiles --------------
__global__ void __launch_bounds__(256)
prep_kernel(const float* __restrict__ feats,
            const float* __restrict__ We1, const float* __restrict__ be1) {
    __shared__ float As2[128][18];
    __shared__ float Bs[16][64];
    int tid = threadIdx.x;
    int tx = tid & 7, ty = tid >> 3;
    int ct = blockIdx.x;
    int half = (ct >= 10);
    int colbase = (half ? ct - 10 : ct) * 64;
    size_t n0 = (size_t)blockIdx.y * 128;
    int wrow0 = half ? 142 : 0;

    u64 acc[4][4];
    #pragma unroll
    for (int i = 0; i < 4; i++)
        #pragma unroll
        for (int j = 0; j < 4; j++) acc[i][j] = 0ull;

    for (int k0 = 0; k0 < DD; k0 += 16) {
        #pragma unroll
        for (int p = 0; p < 4; p++) {
            int idx = tid + p * 256;
            int node = idx >> 3, kp = (idx & 7) * 2;
            int k = k0 + kp;
            float2 v = make_float2(0.f, 0.f);
            if (k < DD)
                v = *(const float2*)(feats + (n0 + node) * DD + k);
            As2[node][kp] = v.x; As2[node][kp+1] = v.y;
        }
        #pragma unroll
        for (int p = 0; p < 2; p++) {
            int idx = tid + p * 256;
            int kk = idx >> 5, cpos = (idx & 31) * 2;
            int k = k0 + kk;
            float2 v = make_float2(0.f, 0.f);
            if (k < DD && colbase + cpos + 1 < EH)
                v = *(const float2*)(We1 + (size_t)(wrow0 + k) * EH + colbase + cpos);
            else if (k < DD && colbase + cpos < EH)
                v.x = We1[(size_t)(wrow0 + k) * EH + colbase + cpos];
            Bs[kk][cpos] = v.x; Bs[kk][cpos+1] = v.y;
        }
        __syncthreads();
        #pragma unroll
        for (int kk = 0; kk < 16; kk++) {
            ulonglong2 w01 = *(const ulonglong2*)&Bs[kk][tx*8];
            ulonglong2 w23 = *(const ulonglong2*)&Bs[kk][tx*8+4];
            #pragma unroll
            for (int i = 0; i < 4; i++) {
                float a = As2[ty*4 + i][kk];
                u64 pa = pack2(a, a);
                fma2(acc[i][0], pa, w01.x);
                fma2(acc[i][1], pa, w01.y);
                fma2(acc[i][2], pa, w23.x);
                fma2(acc[i][3], pa, w23.y);
            }
        }
        __syncthreads();
    }

    float* outp = half ? g_P : g_base;
    #pragma unroll
    for (int i = 0; i < 4; i++) {
        size_t node = n0 + ty*4 + i;
        float ov[8];
        #pragma unroll
        for (int j = 0; j < 4; j++) {
            float2 v = unpack2(acc[i][j]);
            ov[2*j] = v.x; ov[2*j+1] = v.y;
        }
        #pragma unroll
        for (int j = 0; j < 8; j++) {
            int cl = colbase + tx*8 + j;
            float val = 0.f;
            if (cl < EH) {
                val = ov[j];
                if (!half) val += be1[cl];
            }
            ov[j] = val;
        }
        float* op = outp + node * CPAD + colbase + tx*8;
        *(float4*)op       = make_float4(ov[0], ov[1], ov[2], ov[3]);
        *(float4*)(op + 4) = make_float4(ov[4], ov[5], ov[6], ov[7]);
    }
}

// ---------------- kernel 3: per-edge residual + GEMM2 + m_i (2 edges/thread)-
__global__ void __launch_bounds__(ETH)
edge_kernel(const float* __restrict__ We1, const float* __restrict__ We2,
            const float* __restrict__ be2) {
    __shared__ int   sj [RR];
    __shared__ float sdt[RR];
    __shared__ float df_s[RR*24];
    __shared__ float wd_s[21*64];
    __shared__ float we2_s[64*MD];
    __shared__ float base_s[GN*64];
    __shared__ float Ms[RR*MD];

    int tid = threadIdx.x;
    int base_gn = blockIdx.x * GN;
    int b = base_gn >> 11;
    int cg = tid & 3;
    int pp = tid >> 2;
    int g  = pp / 5;
    int pl = pp % 5;
    int e0 = g * 10 + 2 * pl;
    int e1 = e0 + 1;

    if (tid < RR) {
        sj [tid] = g_idx [base_gn*KNB + tid];
        sdt[tid] = g_dist[base_gn*KNB + tid];
    }
    __syncthreads();

    for (int v = tid; v < RR*21; v += ETH) {
        int ee = v / 21, t = v - ee*21;
        float d = sdt[ee];
        float f;
        if (t < 10)      f = sinf(ldexpf(d, -t));
        else if (t < 20) f = cosf(ldexpf(d, -(t-10)));
        else             f = d;
        df_s[ee*24 + t] = f;
    }

    size_t jg0 = (size_t)((b << 11) + sj[e0]);
    size_t jg1 = (size_t)((b << 11) + sj[e1]);
    u64 macc0[8] = {0,0,0,0,0,0,0,0};
    u64 macc1[8] = {0,0,0,0,0,0,0,0};

    for (int chunk = 0; chunk < 10; chunk++) {
        int c0 = chunk * 64;
        for (int v = tid; v < 21*32; v += ETH) {
            int t = v / 32, c = (v - t*32) * 2;
            int col = c0 + c;
            float2 w = make_float2(0.f, 0.f);
            if (col + 1 < EH)
                w = *(const float2*)(We1 + (size_t)(284 + t) * EH + col);
            else if (col < EH)
                w.x = We1[(size_t)(284 + t) * EH + col];
            wd_s[t*64 + c] = w.x; wd_s[t*64 + c + 1] = w.y;
        }
        for (int v = tid; v < 64*MD/4; v += ETH) {
            int off = v * 4;
            int col = c0 + (off >> 4);
            float4 w = make_float4(0.f,0.f,0.f,0.f);
            if (col < EH)
                w = *(const float4*)(We2 + (size_t)c0 * MD + off);
            *(float4*)(we2_s + off) = w;
        }
        for (int v = tid; v < GN*64/4; v += ETH) {
            int off = v * 4;
            int gg = off >> 6;
            *(float4*)(base_s + off) =
                *(const float4*)(g_base + (size_t)(base_gn + gg) * CPAD + c0 + (off & 63));
        }
        __syncthreads();

        const float* bp = base_s + g*64 + cg*16;
        const float4* pr0 = (const float4*)(g_P + jg0 * CPAD + c0 + cg*16);
        const float4* pr1 = (const float4*)(g_P + jg1 * CPAD + c0 + cg*16);
        u64 h0[8], h1[8];
        #pragma unroll
        for (int q = 0; q < 4; q++) {
            float4 p0 = pr0[q], p1 = pr1[q];
            float b0 = bp[4*q], b1 = bp[4*q+1], b2 = bp[4*q+2], b3 = bp[4*q+3];
            h0[2*q]   = pack2(b0 + p0.x, b1 + p0.y);
            h0[2*q+1] = pack2(b2 + p0.z, b3 + p0.w);
            h1[2*q]   = pack2(b0 + p1.x, b1 + p1.y);
            h1[2*q+1] = pack2(b2 + p1.z, b3 + p1.w);
        }

        const float* dfp0 = df_s + e0*24;
        const float* dfp1 = df_s + e1*24;
        #pragma unroll
        for (int t = 0; t < 21; t++) {
            const u64* wr = (const u64*)(wd_s + t*64 + cg*16);
            u64 d0 = pack2(dfp0[t], dfp0[t]);
            u64 d1 = pack2(dfp1[t], dfp1[t]);
            #pragma unroll
            for (int q = 0; q < 8; q++) {
                u64 w = wr[q];
                fma2(h0[q], d0, w);
                fma2(h1[q], d1, w);
            }
        }
        #pragma unroll
        for (int cp = 0; cp < 8; cp++) {
            const u64* wa = (const u64*)(we2_s + (cg*16 + 2*cp) * MD);
            const u64* wb = wa + 8;
            float2 v0 = unpack2(h0[cp]);
            float2 v1 = unpack2(h1[cp]);
            u64 x00 = pack2(silu(v0.x), silu(v0.x));
            u64 x01 = pack2(silu(v0.y), silu(v0.y));
            u64 x10 = pack2(silu(v1.x), silu(v1.x));
            u64 x11 = pack2(silu(v1.y), silu(v1.y));
            #pragma unroll
            for (int mp = 0; mp < 8; mp++) {
                u64 wam = wa[mp], wbm = wb[mp];
                fma2(macc0[mp], x00, wam);
                fma2(macc0[mp], x01, wbm);
                fma2(macc1[mp], x10, wam);
                fma2(macc1[mp], x11, wbm);
            }
        }
        __syncthreads();
    }

    #pragma unroll
    for (int mp = 0; mp < 8; mp++) {
        add2(macc0[mp], __shfl_xor_sync(0xffffffffu, macc0[mp], 1));
        add2(macc0[mp], __shfl_xor_sync(0xffffffffu, macc0[mp], 2));
        add2(macc1[mp], __shfl_xor_sync(0xffffffffu, macc1[mp], 1));
        add2(macc1[mp], __shfl_xor_sync(0xffffffffu, macc1[mp], 2));
    }
    if (cg == 0) {
        #pragma unroll
        for (int mp = 0; mp < 8; mp++) {
            float2 v0 = unpack2(macc0[mp]);
            float2 v1 = unpack2(macc1[mp]);
            float bb0 = be2[2*mp], bb1 = be2[2*mp+1];
            Ms[e0*MD + 2*mp]     = silu(v0.x + bb0);
            Ms[e0*MD + 2*mp + 1] = silu(v0.y + bb1);
            Ms[e1*MD + 2*mp]     = silu(v1.x + bb0);
            Ms[e1*MD + 2*mp + 1] = silu(v1.y + bb1);
        }
    }
    __syncthreads();
    if (tid < GN*MD) {
        int gg = tid >> 4, m = tid & 15;
        float s = 0.f;
        #pragma unroll
        for (int k2 = 0; k2 < KNB; k2++) s += Ms[(gg*KNB + k2)*MD + m];
        g_mi[(size_t)(base_gn + gg)*MD + m] = s;
    }
}

// ---------------- kernel 4: LayerNorm + node MLP stage-1 + partials ---------
// Stage 2 (284->142 GEMM) eliminated: out only needs sum_i h_i and sum_i feats_i
__global__ void __launch_bounds__(256)
node_kernel(const float* __restrict__ feats,
            const float* __restrict__ lng, const float* __restrict__ lnb,
            const float* __restrict__ Wn1, const float* __restrict__ bn1) {
    __shared__ float in_s[8 * 160];
    __shared__ float h_s [8 * 288];
    int tid = threadIdx.x;
    int base_gn = blockIdx.x * 8;
    int w = tid >> 5, lane = tid & 31;

    {
        int gn = base_gn + w;
        const float* fp = feats + (size_t)gn * DD;
        float s = 0.f, ss = 0.f;
        float vals[5];
        #pragma unroll
        for (int u = 0; u < 5; u++) {
            int c = lane + u * 32;
            float v = (c < DD) ? fp[c] : 0.f;
            vals[u] = v; s += v; ss += v * v;
        }
        #pragma unroll
        for (int o = 16; o; o >>= 1) {
            s  += __shfl_xor_sync(0xffffffffu, s,  o);
            ss += __shfl_xor_sync(0xffffffffu, ss, o);
        }
        float mu  = s * (1.f / DD);
        float var = ss * (1.f / DD) - mu * mu;
        float inv = rsqrtf(var + 1e-5f);
        #pragma unroll
        for (int u = 0; u < 5; u++) {
            int c = lane + u * 32;
            if (c < DD) in_s[w * 160 + c] = (vals[u] - mu) * inv * lng[c] + lnb[c];
        }
        if (lane < MD) in_s[w * 160 + DD + lane] = g_mi[(size_t)gn * MD + lane];
    }
    __syncthreads();

    // stage 1: 2 nodes x 4 cols per item; 4 node-pairs * 71 col-groups = 284
    for (int o = tid; o < 284; o += 256) {
        int ng  = o & 3;
        int cgi = o >> 2;
        int c = cgi * 4;
        const float* ip0 = in_s + (2*ng)     * 160;
        const float* ip1 = in_s + (2*ng + 1) * 160;
        u64 a00 = pack2(bn1[c],   bn1[c+1]);
        u64 a01 = pack2(bn1[c+2], bn1[c+3]);
        u64 a10 = a00, a11 = a01;
        #pragma unroll 2
        for (int kk = 0; kk < 158; kk++) {
            ulonglong2 ww = *(const ulonglong2*)(Wn1 + (size_t)kk * 284 + c);
            u64 x0 = pack2(ip0[kk], ip0[kk]);
            u64 x1 = pack2(ip1[kk], ip1[kk]);
            fma2(a00, x0, ww.x); fma2(a01, x0, ww.y);
            fma2(a10, x1, ww.x); fma2(a11, x1, ww.y);
        }
        float2 v;
        float* hp0 = h_s + (2*ng) * 288 + c;
        float* hp1 = hp0 + 288;
        v = unpack2(a00); hp0[0] = silu(v.x); hp0[1] = silu(v.y);
        v = unpack2(a01); hp0[2] = silu(v.x); hp0[3] = silu(v.y);
        v = unpack2(a10); hp1[0] = silu(v.x); hp1[1] = silu(v.y);
        v = unpack2(a11); hp1[2] = silu(v.x); hp1[3] = silu(v.y);
    }
    __syncthreads();

    // partial sums over the 8 nodes: h (284) and feats (142)
    for (int c = tid; c < 284; c += 256) {
        float s = 0.f;
        #pragma unroll
        for (int gg = 0; gg < 8; gg++) s += h_s[gg * 288 + c];
        g_hpart[(size_t)blockIdx.x * 284 + c] = s;
    }
    for (int c = tid; c < DD; c += 256) {
        float s = 0.f;
        #pragma unroll
        for (int gg = 0; gg < 8; gg++) s += feats[(size_t)(base_gn + gg) * DD + c];
        g_fpart[(size_t)blockIdx.x * DD + c] = s;
    }
}

// ---------------- kernel 5: pool + folded stage-2 + head ---------------------
// out_b = [ H@ (Wn2@Wout) + F@Wout ] / N + bn2@Wout + bout
__global__ void __launch_bounds__(256)
head_kernel(const float* __restrict__ Wn2, const float* __restrict__ bn2,
            const float* __restrict__ Wout, const float* __restrict__ bout,
            float* __restrict__ out) {
    __shared__ float H[284];
    __shared__ float F[DD];
    __shared__ float red[256];
    int b = blockIdx.x, tid = threadIdx.x;
    const int bpb = NN / 8;  // 256 blocks per batch

    for (int c = tid; c < 284; c += 256) {
        float s = 0.f;
        const float* pp = g_hpart + ((size_t)b * bpb) * 284 + c;
        for (int blk = 0; blk < bpb; blk++) s += pp[(size_t)blk * 284];
        H[c] = s;
    }
    for (int c = tid; c < DD; c += 256) {
        float s = 0.f;
        const float* pp = g_fpart + ((size_t)b * bpb) * DD + c;
        for (int blk = 0; blk < bpb; blk++) s += pp[(size_t)blk * DD];
        F[c] = s;
    }
    __syncthreads();

    float acc = 0.f;
    for (int c = tid; c < 284; c += 256) {
        const float* wr = Wn2 + (size_t)c * DD;
        float w2o = 0.f;
        for (int d = 0; d < DD; d++) w2o += wr[d] * Wout[d];
        acc += H[c] * w2o;
    }
    for (int d = tid; d < DD; d += 256)
        acc += (F[d] + (float)NN * bn2[d]) * Wout[d];
    red[tid] = acc;
    __syncthreads();
    for (int s2 = 128; s2 > 0; s2 >>= 1) {
        if (tid < s2) red[tid] += red[tid + s2];
        __syncthreads();
    }
    if (tid == 0) out[b] = red[0] * (1.f / (float)NN) + bout[0];
}

// ---------------- launch ----------------------------------------------------
extern "C" void kernel_launch(void* const* d_in, const int* in_sizes, int n_in,
                              void* d_out, int out_size) {
    const float* feats = (const float*)d_in[0];
    const float* coors = (const float*)d_in[1];
    const float* We1  = (const float*)d_in[3];
    const float* be1  = (const float*)d_in[4];
    const float* We2  = (const float*)d_in[5];
    const float* be2  = (const float*)d_in[6];
    const float* lng  = (const float*)d_in[11];
    const float* lnb  = (const float*)d_in[12];
    const float* Wn1  = (const float*)d_in[13];
    const float* bn1  = (const float*)d_in[14];
    const float* Wn2  = (const float*)d_in[15];
    const float* bn2  = (const float*)d_in[16];
    const float* Wout = (const float*)d_in[17];
    const float* bout = (const float*)d_in[18];
    float* out = (float*)d_out;

    knn_kernel<<<BB * NN, 256>>>(coors);
    dim3 pg(20, 256);
    prep_kernel<<<pg, 256>>>(feats, We1, be1);
    edge_kernel<<<(BB * NN) / GN, ETH>>>(We1, We2, be2);
    node_kernel<<<(BB * NN) / 8, 256>>>(feats, lng, lnb, Wn1, bn1);
    head_kernel<<<BB, 256>>>(Wn2, bn2, Wout, bout, out);
}